// round 4
// baseline (speedup 1.0000x reference)
#include <cuda_runtime.h>
#include <math.h>
#include <stdint.h>

// ---------------- problem constants ----------------
#define NBATCH 4096
#define NTOK   64
#define MTOT   (NBATCH * NTOK)
#define DOBS   128
#define DMSG   64
#define DINT   256

// ---------------- shared-memory layout (floats) ----------------
// Header: biases + LN params
//  [0..127] enc_b1  [128..191] enc_b2  [192..383] inp_b  [384..447] out_b
//  [448..703] int_b1  [704..831] int_b2  [832..1087] ln_g  [1088..1343] ln_b
#define HDR      1344
#define LD_OBS   132     // all activation LDs = 4 (mod 32) -> conflict-free A frags
#define LD_H     132
#define LD_MSG   68
#define LD_QKV   196
#define LD_CTX   68
#define LD_AGG   68
#define LD_Z     260

#define OFF_OBS  1344            // 64*132 = 8448
#define OFF_H    9792            // 8448
#define OFF_MSG  18240           // 64*68 = 4352
#define OFF_QKV  22592           // 64*196 = 12544 -> end 35136
#define OFF_CTX  9792            // alias H (dead after enc2->msg)
#define OFF_AGG  14144           // 4352 (inside old H/MSG dead space)
#define OFF_Z    18496           // 64*260 = 16640 -> end 35136 (alias QKV/MSG, dead)
#define SMEM_FLOATS 35136
#define SMEM_BYTES  (SMEM_FLOATS * 4)

// ---------------- packed tf32 weight buffer (fragment-ordered) ----------------
// For each (kstep kk, ntile j): 32 lanes * float2 {W[k0+t][n0+g], W[k0+t+4][n0+g]}
#define P_E1  0                      // 128x128 -> 16384 floats
#define P_E2  16384                  // 128x64  ->  8192
#define P_QK  24576                  // 64x192  -> 12288
#define P_OP  36864                  // 64x64   ->  4096
#define P_I1  40960                  // 192x256 -> 49152
#define P_I2  90112                  // 256x128 -> 32768
#define P_TOT 122880
__device__ float g_pack[P_TOT];
__device__ float g_msgs_s[(size_t)MTOT * DMSG];   // msgs fallback

// ---------------- helpers ----------------
__device__ __forceinline__ uint32_t f2tf(float x) {
    uint32_t u;
    asm("cvt.rna.tf32.f32 %0, %1;" : "=r"(u) : "f"(x));
    return u;
}

// packer: one thread per B-fragment pair
__global__ void pack_w(const float* __restrict__ W, int K, int N, float* __restrict__ dst)
{
    int gid = blockIdx.x * blockDim.x + threadIdx.x;
    int total = K * N / 2;
    if (gid >= total) return;
    int lane = gid & 31;
    int tile = gid >> 5;                 // kk*(N/8) + j
    int nt = N >> 3;
    int j = tile % nt, kk = tile / nt;
    int t = lane & 3, g = lane >> 2;
    int k = kk * 8 + t, n = j * 8 + g;
    float2 v;
    v.x = __uint_as_float(f2tf(W[(size_t)k * N + n]));
    v.y = __uint_as_float(f2tf(W[(size_t)(k + 4) * N + n]));
    ((float2*)dst)[gid] = v;
}

// ---------------- warp-tiled tf32 mma stage ----------------
// Y[64 x N] = relu?(X[64 x K] @ W + bias); X optionally concat of sX (KSPLIT cols) | sX2.
// 8 warps: rows 16*(wid&3), column half (wid>>2). LDY may address gmem (int2).
template<int K, int N, int LDX, int LDX2, int KSPLIT, int LDY, bool RELU>
__device__ __forceinline__ void mma_stage(int tid, const float* sX, const float* sX2,
                                          const float* __restrict__ packB,
                                          const float* sBias, float* sY)
{
    const int lane = tid & 31, wid = tid >> 5;
    const int r0 = (wid & 3) * 16;
    const int ch = wid >> 2;
    const int t = lane & 3, g = lane >> 2;
    constexpr int NT = N / 16;          // n8-tiles per warp
    constexpr int KS1 = (KSPLIT ? KSPLIT : K) / 8;
    float acc[NT][4];
#pragma unroll
    for (int j = 0; j < NT; j++)
        acc[j][0] = acc[j][1] = acc[j][2] = acc[j][3] = 0.f;
    const float2* bp = (const float2*)packB;

#pragma unroll 2
    for (int kk = 0; kk < KS1; kk++) {
        const int kb = kk * 8;
        uint32_t a0 = f2tf(sX[(r0 + g) * LDX + kb + t]);
        uint32_t a1 = f2tf(sX[(r0 + g + 8) * LDX + kb + t]);
        uint32_t a2 = f2tf(sX[(r0 + g) * LDX + kb + t + 4]);
        uint32_t a3 = f2tf(sX[(r0 + g + 8) * LDX + kb + t + 4]);
#pragma unroll
        for (int j = 0; j < NT; j++) {
            float2 bv = bp[(kk * (N / 8) + ch * NT + j) * 32 + lane];
            asm volatile("mma.sync.aligned.m16n8k8.row.col.f32.tf32.tf32.f32 "
                         "{%0,%1,%2,%3}, {%4,%5,%6,%7}, {%8,%9}, {%0,%1,%2,%3};"
                         : "+f"(acc[j][0]), "+f"(acc[j][1]), "+f"(acc[j][2]), "+f"(acc[j][3])
                         : "r"(a0), "r"(a1), "r"(a2), "r"(a3),
                           "r"(__float_as_uint(bv.x)), "r"(__float_as_uint(bv.y)));
        }
    }
    if (KSPLIT) {
#pragma unroll 2
        for (int kk = KS1; kk < K / 8; kk++) {
            const int kb = kk * 8 - KSPLIT;
            uint32_t a0 = f2tf(sX2[(r0 + g) * LDX2 + kb + t]);
            uint32_t a1 = f2tf(sX2[(r0 + g + 8) * LDX2 + kb + t]);
            uint32_t a2 = f2tf(sX2[(r0 + g) * LDX2 + kb + t + 4]);
            uint32_t a3 = f2tf(sX2[(r0 + g + 8) * LDX2 + kb + t + 4]);
#pragma unroll
            for (int j = 0; j < NT; j++) {
                float2 bv = bp[(kk * (N / 8) + ch * NT + j) * 32 + lane];
                asm volatile("mma.sync.aligned.m16n8k8.row.col.f32.tf32.tf32.f32 "
                             "{%0,%1,%2,%3}, {%4,%5,%6,%7}, {%8,%9}, {%0,%1,%2,%3};"
                             : "+f"(acc[j][0]), "+f"(acc[j][1]), "+f"(acc[j][2]), "+f"(acc[j][3])
                             : "r"(a0), "r"(a1), "r"(a2), "r"(a3),
                               "r"(__float_as_uint(bv.x)), "r"(__float_as_uint(bv.y)));
            }
        }
    }
#pragma unroll
    for (int j = 0; j < NT; j++) {
        const int n0 = (ch * NT + j) * 8;
        const float b0 = sBias[n0 + 2 * t], b1 = sBias[n0 + 2 * t + 1];
        float v0 = acc[j][0] + b0, v1 = acc[j][1] + b1;
        float v2 = acc[j][2] + b0, v3 = acc[j][3] + b1;
        if (RELU) { v0 = fmaxf(v0, 0.f); v1 = fmaxf(v1, 0.f); v2 = fmaxf(v2, 0.f); v3 = fmaxf(v3, 0.f); }
        *(float2*)(sY + (size_t)(r0 + g) * LDY + n0 + 2 * t)     = make_float2(v0, v1);
        *(float2*)(sY + (size_t)(r0 + g + 8) * LDY + n0 + 2 * t) = make_float2(v2, v3);
    }
}

// ---------------- fused kernel: one CTA per batch ----------------
extern __shared__ float smem[];

__global__ void __launch_bounds__(256)
fused_kernel(const float* __restrict__ obs,
             const float* __restrict__ enc_b1, const float* __restrict__ enc_b2,
             const float* __restrict__ inp_b,  const float* __restrict__ out_b,
             const float* __restrict__ int_b1, const float* __restrict__ int_b2,
             const float* __restrict__ ln_g,   const float* __restrict__ ln_b,
             const float* __restrict__ pack,
             float* __restrict__ outE, float* __restrict__ outM)
{
    const int b = blockIdx.x;
    const int tid = threadIdx.x;

    // ---- header: biases + LN params ----
    for (int i = tid; i < 128; i += 256) smem[i] = enc_b1[i];
    for (int i = tid; i < 64;  i += 256) smem[128 + i] = enc_b2[i];
    for (int i = tid; i < 192; i += 256) smem[192 + i] = inp_b[i];
    for (int i = tid; i < 64;  i += 256) smem[384 + i] = out_b[i];
    for (int i = tid; i < 256; i += 256) smem[448 + i] = int_b1[i];
    for (int i = tid; i < 128; i += 256) smem[704 + i] = int_b2[i];
    for (int i = tid; i < 256; i += 256) smem[832 + i] = ln_g[i];
    for (int i = tid; i < 256; i += 256) smem[1088 + i] = ln_b[i];

    // ---- load obs tile into padded smem (rows of 128 floats, LD 132) ----
    {
        const float4* g4 = (const float4*)(obs + (size_t)b * NTOK * DOBS);
        for (int i = tid; i < NTOK * DOBS / 4; i += 256) {
            int r = i >> 5, c4 = i & 31;   // 32 float4 per row
            *(float4*)(smem + OFF_OBS + r * LD_OBS + c4 * 4) = g4[i];
        }
    }
    __syncthreads();

    // ---- enc1: h = relu(obs @ W1 + b1) ----
    mma_stage<128, 128, LD_OBS, 0, 0, LD_H, true>(tid, smem + OFF_OBS, nullptr,
        pack + P_E1, smem + 0, smem + OFF_H);
    __syncthreads();

    // ---- enc2: msgs = h @ W2 + b2 ----
    mma_stage<128, 64, LD_H, 0, 0, LD_MSG, false>(tid, smem + OFF_H, nullptr,
        pack + P_E2, smem + 128, smem + OFF_MSG);
    __syncthreads();

    // ---- msgs -> gmem (second output) ----
    if (outM) {
        float4* gm = (float4*)(outM + (size_t)b * NTOK * DMSG);
        for (int i = tid; i < NTOK * DMSG / 4; i += 256) {
            int r = i >> 4, c4 = i & 15;
            gm[i] = *(const float4*)(smem + OFF_MSG + r * LD_MSG + c4 * 4);
        }
    }

    // ---- qkv = msgs @ in_proj + b ----
    mma_stage<64, 192, LD_MSG, 0, 0, LD_QKV, false>(tid, smem + OFF_MSG, nullptr,
        pack + P_QK, smem + 192, smem + OFF_QKV);
    __syncthreads();

    // ---- attention: thread = (head, query); 2-pass recompute softmax ----
    {
        const int h = tid >> 6, q = tid & 63;
        const float* sQ = smem + OFF_QKV;
        float qv[16];
#pragma unroll
        for (int d = 0; d < 16; d++) qv[d] = sQ[q * LD_QKV + h * 16 + d];
        float m = -1e30f;
#pragma unroll 4
        for (int k = 0; k < 64; k++) {
            const float* kp = sQ + k * LD_QKV + 64 + h * 16;
            float s = 0.f;
#pragma unroll
            for (int d = 0; d < 16; d++) s = fmaf(qv[d], kp[d], s);
            m = fmaxf(m, s * 0.25f);
        }
        float ssum = 0.f, ctx[16];
#pragma unroll
        for (int d = 0; d < 16; d++) ctx[d] = 0.f;
#pragma unroll 2
        for (int k = 0; k < 64; k++) {
            const float* kp = sQ + k * LD_QKV + 64 + h * 16;
            float s = 0.f;
#pragma unroll
            for (int d = 0; d < 16; d++) s = fmaf(qv[d], kp[d], s);
            float p = __expf(fmaf(s, 0.25f, -m));
            ssum += p;
            const float* vp = sQ + k * LD_QKV + 128 + h * 16;
#pragma unroll
            for (int d = 0; d < 16; d++) ctx[d] = fmaf(p, vp[d], ctx[d]);
        }
        float inv = 1.f / ssum;
        float* so = smem + OFF_CTX;
#pragma unroll
        for (int d = 0; d < 16; d++) so[q * LD_CTX + h * 16 + d] = ctx[d] * inv;
    }
    __syncthreads();

    // ---- out projection: agg = ctx @ out_w + out_b ----
    mma_stage<64, 64, LD_CTX, 0, 0, LD_AGG, false>(tid, smem + OFF_CTX, nullptr,
        pack + P_OP, smem + 384, smem + OFF_AGG);
    __syncthreads();

    // ---- int1: z = [obs | agg] @ int_w1 + int_b1 (no relu; LN first) ----
    mma_stage<192, 256, LD_OBS, LD_AGG, 128, LD_Z, false>(tid, smem + OFF_OBS,
        smem + OFF_AGG, pack + P_I1, smem + 448, smem + OFF_Z);
    __syncthreads();

    // ---- LayerNorm(256) + ReLU in place. 4 threads per token. ----
    {
        const int t = tid >> 2, s = tid & 3;
        float* zr = smem + OFF_Z + t * LD_Z;
        float sum = 0.f, sq = 0.f;
#pragma unroll
        for (int i = 0; i < 64; i++) {
            float v = zr[s + 4 * i];
            sum += v;
            sq = fmaf(v, v, sq);
        }
        sum += __shfl_xor_sync(0xffffffffu, sum, 1);
        sum += __shfl_xor_sync(0xffffffffu, sum, 2);
        sq  += __shfl_xor_sync(0xffffffffu, sq, 1);
        sq  += __shfl_xor_sync(0xffffffffu, sq, 2);
        float mu   = sum * (1.f / 256.f);
        float var  = sq * (1.f / 256.f) - mu * mu;
        float rstd = rsqrtf(var + 1e-5f);
        const float* gmm = smem + 832;
        const float* bet = smem + 1088;
#pragma unroll
        for (int i = 0; i < 64; i++) {
            int c = s + 4 * i;
            float v = zr[c];
            v = (v - mu) * rstd * gmm[c] + bet[c];
            zr[c] = fmaxf(v, 0.f);
        }
    }
    __syncthreads();

    // ---- int2: enriched = z @ int_w2 + int_b2 -> gmem directly ----
    mma_stage<256, 128, LD_Z, 0, 0, 128, false>(tid, smem + OFF_Z, nullptr,
        pack + P_I2, smem + 704, outE + (size_t)b * NTOK * DOBS);
}

// ---------------- launch ----------------
extern "C" void kernel_launch(void* const* d_in, const int* in_sizes, int n_in,
                              void* d_out, int out_size)
{
    const float* obs    = (const float*)d_in[0];
    const float* enc_w1 = (const float*)d_in[1];
    const float* enc_b1 = (const float*)d_in[2];
    const float* enc_w2 = (const float*)d_in[3];
    const float* enc_b2 = (const float*)d_in[4];
    const float* inp_w  = (const float*)d_in[5];
    const float* inp_b  = (const float*)d_in[6];
    const float* out_w  = (const float*)d_in[7];
    const float* out_b  = (const float*)d_in[8];
    const float* int_w1 = (const float*)d_in[9];
    const float* int_b1 = (const float*)d_in[10];
    const float* ln_g   = (const float*)d_in[11];
    const float* ln_b   = (const float*)d_in[12];
    const float* int_w2 = (const float*)d_in[13];
    const float* int_b2 = (const float*)d_in[14];

    float* outE = (float*)d_out;
    const size_t esz = (size_t)MTOT * DOBS;
    float* outM = ((size_t)out_size > esz) ? outE + esz : nullptr;

    float* p_pack;
    float* p_msgs;
    cudaGetSymbolAddress((void**)&p_pack, g_pack);
    cudaGetSymbolAddress((void**)&p_msgs, g_msgs_s);
    if (!outM) outM = p_msgs;  // keep behavior deterministic

    // ---- pack weights into tf32 fragment order (tiny, per launch) ----
    pack_w<<<32, 256>>>(enc_w1, 128, 128, p_pack + P_E1);
    pack_w<<<16, 256>>>(enc_w2, 128, 64,  p_pack + P_E2);
    pack_w<<<24, 256>>>(inp_w,  64,  192, p_pack + P_QK);
    pack_w<<<8,  256>>>(out_w,  64,  64,  p_pack + P_OP);
    pack_w<<<96, 256>>>(int_w1, 192, 256, p_pack + P_I1);
    pack_w<<<64, 256>>>(int_w2, 256, 128, p_pack + P_I2);

    cudaFuncSetAttribute(fused_kernel, cudaFuncAttributeMaxDynamicSharedMemorySize, SMEM_BYTES);
    fused_kernel<<<NBATCH, 256, SMEM_BYTES>>>(
        obs, enc_b1, enc_b2, inp_b, out_b, int_b1, int_b2, ln_g, ln_b,
        p_pack, outE, outM);
}

// round 5
// speedup vs baseline: 3.9617x; 3.9617x over previous
#include <cuda_runtime.h>
#include <math.h>
#include <stdint.h>

// ---------------- problem constants ----------------
#define NBATCH 4096
#define NTOK   64
#define MTOT   (NBATCH * NTOK)
#define DOBS   128
#define DMSG   64

// ---------------- packed tf32 weight buffers ----------------
// fragment layout per (kk, j) tile: 32 lanes x float2 {W[k0+t][n0+g], W[k0+4+t][n0+g]}
#define P_E1  0                      // 128x128 -> 16384 floats
#define P_E2  16384                  // 128x64  ->  8192
#define P_QK  24576                  // 64x192  -> 12288
#define P_I1  36864                  // 192x256 -> 49152 (combined: int_w1[0:128]; out_w@int_w1[128:192])
#define P_I2  86016                  // 256x128 -> 32768
#define P_TOT 118784
__device__ float g_pack[P_TOT];
__device__ float g_Wc[64 * 256];
__device__ float g_bc[256];
__device__ float g_Wcomb[192 * 256];
__device__ float g_h[(size_t)MTOT * 128];
__device__ float g_qkv[(size_t)MTOT * 192];
__device__ float g_ctx[(size_t)MTOT * 64];
__device__ float g_z[(size_t)MTOT * 256];
__device__ float g_msgs_s[(size_t)MTOT * 64];

// ---------------- helpers ----------------
__device__ __forceinline__ uint32_t f2tf(float x) {
    uint32_t u;
    asm("cvt.rna.tf32.f32 %0, %1;" : "=r"(u) : "f"(x));
    return u;
}
__device__ __forceinline__ uint32_t smem_u32(const void* p) {
    uint32_t a;
    asm("{ .reg .u64 t; cvta.to.shared.u64 t, %1; cvt.u32.u64 %0, t; }" : "=r"(a) : "l"(p));
    return a;
}
__device__ __forceinline__ void cp16(uint32_t dst, const float* src) {
    asm volatile("cp.async.ca.shared.global [%0], [%1], 16;" :: "r"(dst), "l"(src));
}
#define CP_COMMIT() asm volatile("cp.async.commit_group;" ::: "memory")
#define CP_WAIT(n)  asm volatile("cp.async.wait_group %0;" :: "n"(n) : "memory")

#define MMA_TF32(acc, a, bx, by)                                                     \
    asm volatile("mma.sync.aligned.m16n8k8.row.col.f32.tf32.tf32.f32 "               \
                 "{%0,%1,%2,%3}, {%4,%5,%6,%7}, {%8,%9}, {%0,%1,%2,%3};"             \
                 : "+f"((acc)[0]), "+f"((acc)[1]), "+f"((acc)[2]), "+f"((acc)[3])    \
                 : "r"((a)[0]), "r"((a)[1]), "r"((a)[2]), "r"((a)[3]),               \
                   "r"(bx), "r"(by))

// ---------------- weight prep (tiny, per launch) ----------------
__global__ void pack_w(const float* __restrict__ W, int K, int N, float* __restrict__ dst)
{
    int gid = blockIdx.x * blockDim.x + threadIdx.x;
    int total = K * N / 2;
    if (gid >= total) return;
    int lane = gid & 31;
    int tile = gid >> 5;
    int nt = N >> 3;
    int j = tile % nt, kk = tile / nt;
    int t = lane & 3, g = lane >> 2;
    int k = kk * 8 + t, n = j * 8 + g;
    float2 v;
    v.x = __uint_as_float(f2tf(W[(size_t)k * N + n]));
    v.y = __uint_as_float(f2tf(W[(size_t)(k + 4) * N + n]));
    ((float2*)dst)[gid] = v;
}

__global__ void prep_wc(const float* __restrict__ out_w, const float* __restrict__ out_b,
                        const float* __restrict__ int_w1, const float* __restrict__ int_b1)
{
    int i = blockIdx.x * blockDim.x + threadIdx.x;
    if (i < 64 * 256) {
        int c = i >> 8, n = i & 255;
        float s = 0.f;
        for (int m = 0; m < 64; m++) s = fmaf(out_w[c * 64 + m], int_w1[(128 + m) * 256 + n], s);
        g_Wc[i] = s;
    }
    if (i < 256) {
        float s = int_b1[i];
        for (int m = 0; m < 64; m++) s = fmaf(out_b[m], int_w1[(128 + m) * 256 + i], s);
        g_bc[i] = s;
    }
}

__global__ void combine_w(const float* __restrict__ int_w1)
{
    int i = blockIdx.x * blockDim.x + threadIdx.x;
    if (i >= 192 * 256) return;
    int row = i >> 8;
    g_Wcomb[i] = (row < 128) ? int_w1[i] : g_Wc[i - 128 * 256];
}

// ---------------- pipelined tf32 GEMM ----------------
// out[MTOT x N] = epi(A[MTOT x K] @ W + bias). CTA = 64 rows, 256 threads, 8 warps (2 row x 4 col).
// A optionally concat: cols >= KSPLIT come from A1. MODE: 0 none, 1 relu, 2 LayerNorm+relu.
template<int K, int N, int KSPLIT, int MODE>
__global__ void __launch_bounds__(256)
gemm_pipe(const float* __restrict__ A0, int strideA0,
          const float* __restrict__ A1, int strideA1,
          const float* __restrict__ packB,
          const float* __restrict__ bias,
          const float* __restrict__ lng, const float* __restrict__ lnb,
          float* __restrict__ out)
{
    extern __shared__ float sm[];
    constexpr int NCH = K / 32;          // K chunks of 32
    constexpr int NT  = N / 32;          // n8 tiles per warp
    constexpr int SA  = 64 * 36;         // A chunk floats (LD 36, pad -> conflict free)
    constexpr int SB  = 32 * N;          // B chunk floats (packed fragment order)
    constexpr int OFF_A = 768;
    constexpr int OFF_B = OFF_A + 2 * SA;
    constexpr int OFF_R = OFF_B + 2 * SB;

    const int tid = threadIdx.x;
    const int m0  = blockIdx.x * 64;
    const uint32_t sbase = smem_u32(sm);

    // header: bias (+ LN params)
    for (int i = tid; i < N; i += 256) sm[i] = bias[i];
    if (MODE == 2)
        for (int i = tid; i < N; i += 256) { sm[256 + i] = lng[i]; sm[512 + i] = lnb[i]; }

    const int lane = tid & 31, w = tid >> 5;
    const int wr = w >> 2, wc = w & 3;
    const int t = lane & 3, g = lane >> 2;
    const int r0 = wr * 32;

    float acc[2][NT][4];
#pragma unroll
    for (int mt = 0; mt < 2; mt++)
#pragma unroll
        for (int j = 0; j < NT; j++)
            acc[mt][j][0] = acc[mt][j][1] = acc[mt][j][2] = acc[mt][j][3] = 0.f;

    auto issue = [&](int c, int buf) {
        const int gc0 = c * 32;
        // A chunk: 64 rows x 32 cols, 16B per op
#pragma unroll
        for (int e = tid; e < 512; e += 256) {
            int row = e >> 3, cq = e & 7;
            int gcol = gc0 + cq * 4;
            const float* src;
            if (KSPLIT && gcol >= KSPLIT)
                src = A1 + (size_t)(m0 + row) * strideA1 + (gcol - KSPLIT);
            else
                src = A0 + (size_t)(m0 + row) * strideA0 + gcol;
            cp16(sbase + (uint32_t)(OFF_A + buf * SA + row * 36 + cq * 4) * 4, src);
        }
        // B chunk: contiguous in packed buffer
        const float* bs = packB + (size_t)c * SB;
        for (int e = tid; e < SB / 4; e += 256)
            cp16(sbase + (uint32_t)(OFF_B + buf * SB) * 4 + (uint32_t)e * 16, bs + e * 4);
    };

    issue(0, 0);
    CP_COMMIT();

#pragma unroll 1
    for (int c = 0; c < NCH; c++) {
        if (c + 1 < NCH) { issue(c + 1, (c + 1) & 1); CP_COMMIT(); CP_WAIT(1); }
        else             { CP_WAIT(0); }
        __syncthreads();

        const float*  sA  = sm + OFF_A + (c & 1) * SA;
        const float2* sBf = (const float2*)(sm + OFF_B + (c & 1) * SB);
#pragma unroll
        for (int kl = 0; kl < 4; kl++) {
            uint32_t a[2][4];
#pragma unroll
            for (int mt = 0; mt < 2; mt++) {
                const int rb = r0 + mt * 16 + g;
                a[mt][0] = f2tf(sA[rb * 36 + kl * 8 + t]);
                a[mt][1] = f2tf(sA[(rb + 8) * 36 + kl * 8 + t]);
                a[mt][2] = f2tf(sA[rb * 36 + kl * 8 + t + 4]);
                a[mt][3] = f2tf(sA[(rb + 8) * 36 + kl * 8 + t + 4]);
            }
#pragma unroll
            for (int j = 0; j < NT; j++) {
                float2 bv = sBf[(size_t)(kl * (N / 8) + wc * NT + j) * 32 + lane];
                const uint32_t bx = __float_as_uint(bv.x), by = __float_as_uint(bv.y);
#pragma unroll
                for (int mt = 0; mt < 2; mt++)
                    MMA_TF32(acc[mt][j], a[mt], bx, by);
            }
        }
        __syncthreads();
    }

    // ---------------- epilogue ----------------
    if (MODE == 2) {
        // bias add
#pragma unroll
        for (int mt = 0; mt < 2; mt++)
#pragma unroll
            for (int j = 0; j < NT; j++) {
                const int n0 = wc * (N / 4) + j * 8 + 2 * t;
                acc[mt][j][0] += sm[n0];     acc[mt][j][1] += sm[n0 + 1];
                acc[mt][j][2] += sm[n0];     acc[mt][j][3] += sm[n0 + 1];
            }
        // per-(mt,half) partial sums over this warp's cols
        float ps[2][2] = {{0,0},{0,0}}, pq[2][2] = {{0,0},{0,0}};
#pragma unroll
        for (int mt = 0; mt < 2; mt++)
#pragma unroll
            for (int j = 0; j < NT; j++) {
                ps[mt][0] += acc[mt][j][0] + acc[mt][j][1];
                pq[mt][0] += acc[mt][j][0] * acc[mt][j][0] + acc[mt][j][1] * acc[mt][j][1];
                ps[mt][1] += acc[mt][j][2] + acc[mt][j][3];
                pq[mt][1] += acc[mt][j][2] * acc[mt][j][2] + acc[mt][j][3] * acc[mt][j][3];
            }
#pragma unroll
        for (int mt = 0; mt < 2; mt++)
#pragma unroll
            for (int h = 0; h < 2; h++) {
                ps[mt][h] += __shfl_xor_sync(0xffffffffu, ps[mt][h], 1);
                ps[mt][h] += __shfl_xor_sync(0xffffffffu, ps[mt][h], 2);
                pq[mt][h] += __shfl_xor_sync(0xffffffffu, pq[mt][h], 1);
                pq[mt][h] += __shfl_xor_sync(0xffffffffu, pq[mt][h], 2);
            }
        if (t == 0) {
#pragma unroll
            for (int mt = 0; mt < 2; mt++)
#pragma unroll
                for (int h = 0; h < 2; h++) {
                    const int rl = r0 + mt * 16 + g + 8 * h;
                    sm[OFF_R + rl * 4 + wc]       = ps[mt][h];
                    sm[OFF_R + 256 + rl * 4 + wc] = pq[mt][h];
                }
        }
        __syncthreads();
        float mu[2][2], rs[2][2];
#pragma unroll
        for (int mt = 0; mt < 2; mt++)
#pragma unroll
            for (int h = 0; h < 2; h++) {
                const int rl = r0 + mt * 16 + g + 8 * h;
                float s_ = sm[OFF_R + rl * 4] + sm[OFF_R + rl * 4 + 1]
                         + sm[OFF_R + rl * 4 + 2] + sm[OFF_R + rl * 4 + 3];
                float q_ = sm[OFF_R + 256 + rl * 4] + sm[OFF_R + 256 + rl * 4 + 1]
                         + sm[OFF_R + 256 + rl * 4 + 2] + sm[OFF_R + 256 + rl * 4 + 3];
                float m_ = s_ * (1.f / N);
                float v_ = q_ * (1.f / N) - m_ * m_;
                mu[mt][h] = m_;
                rs[mt][h] = rsqrtf(v_ + 1e-5f);
            }
#pragma unroll
        for (int mt = 0; mt < 2; mt++)
#pragma unroll
            for (int j = 0; j < NT; j++) {
                const int n0 = wc * (N / 4) + j * 8 + 2 * t;
                const float g0 = sm[256 + n0], g1 = sm[256 + n0 + 1];
                const float b0 = sm[512 + n0], b1 = sm[512 + n0 + 1];
                float v0 = fmaxf((acc[mt][j][0] - mu[mt][0]) * rs[mt][0] * g0 + b0, 0.f);
                float v1 = fmaxf((acc[mt][j][1] - mu[mt][0]) * rs[mt][0] * g1 + b1, 0.f);
                float v2 = fmaxf((acc[mt][j][2] - mu[mt][1]) * rs[mt][1] * g0 + b0, 0.f);
                float v3 = fmaxf((acc[mt][j][3] - mu[mt][1]) * rs[mt][1] * g1 + b1, 0.f);
                const size_t rA = (size_t)(m0 + r0 + mt * 16 + g);
                *(float2*)(out + rA * N + n0)       = make_float2(v0, v1);
                *(float2*)(out + (rA + 8) * N + n0) = make_float2(v2, v3);
            }
    } else {
#pragma unroll
        for (int mt = 0; mt < 2; mt++)
#pragma unroll
            for (int j = 0; j < NT; j++) {
                const int n0 = wc * (N / 4) + j * 8 + 2 * t;
                const float b0 = sm[n0], b1 = sm[n0 + 1];
                float v0 = acc[mt][j][0] + b0, v1 = acc[mt][j][1] + b1;
                float v2 = acc[mt][j][2] + b0, v3 = acc[mt][j][3] + b1;
                if (MODE == 1) {
                    v0 = fmaxf(v0, 0.f); v1 = fmaxf(v1, 0.f);
                    v2 = fmaxf(v2, 0.f); v3 = fmaxf(v3, 0.f);
                }
                const size_t rA = (size_t)(m0 + r0 + mt * 16 + g);
                *(float2*)(out + rA * N + n0)       = make_float2(v0, v1);
                *(float2*)(out + (rA + 8) * N + n0) = make_float2(v2, v3);
            }
    }
}

// ---------------- attention (scalar fp32, validated) ----------------
#define LD_QKV 196
#define LD_CTX 68
__global__ void __launch_bounds__(256)
attn_kernel(const float* __restrict__ qkv, float* __restrict__ ctxo)
{
    extern __shared__ float smA[];
    float* sQ = smA;
    float* sC = smA + 64 * LD_QKV;
    const int b = blockIdx.x, tid = threadIdx.x;
    const float* src = qkv + (size_t)b * 64 * 192;
    for (int i = tid; i < 64 * 192 / 4; i += 256) {
        int r = i / 48, c4 = i - r * 48;
        *(float4*)(sQ + r * LD_QKV + c4 * 4) = *(const float4*)(src + r * 192 + c4 * 4);
    }
    __syncthreads();
    {
        const int h = tid >> 6, q = tid & 63;
        float qv[16];
#pragma unroll
        for (int d = 0; d < 16; d++) qv[d] = sQ[q * LD_QKV + h * 16 + d];
        float m = -1e30f;
#pragma unroll 4
        for (int k = 0; k < 64; k++) {
            const float* kp = sQ + k * LD_QKV + 64 + h * 16;
            float s = 0.f;
#pragma unroll
            for (int d = 0; d < 16; d++) s = fmaf(qv[d], kp[d], s);
            m = fmaxf(m, s * 0.25f);
        }
        float ssum = 0.f, ctx[16];
#pragma unroll
        for (int d = 0; d < 16; d++) ctx[d] = 0.f;
#pragma unroll 2
        for (int k = 0; k < 64; k++) {
            const float* kp = sQ + k * LD_QKV + 64 + h * 16;
            float s = 0.f;
#pragma unroll
            for (int d = 0; d < 16; d++) s = fmaf(qv[d], kp[d], s);
            float p = __expf(fmaf(s, 0.25f, -m));
            ssum += p;
            const float* vp = sQ + k * LD_QKV + 128 + h * 16;
#pragma unroll
            for (int d = 0; d < 16; d++) ctx[d] = fmaf(p, vp[d], ctx[d]);
        }
        float inv = 1.f / ssum;
#pragma unroll
        for (int d = 0; d < 16; d++) sC[q * LD_CTX + h * 16 + d] = ctx[d] * inv;
    }
    __syncthreads();
    float* go = ctxo + (size_t)b * 64 * 64;
    for (int i = tid; i < 64 * 64; i += 256) {
        int r = i >> 6, c = i & 63;
        go[i] = sC[r * LD_CTX + c];
    }
}

// ---------------- launch ----------------
extern "C" void kernel_launch(void* const* d_in, const int* in_sizes, int n_in,
                              void* d_out, int out_size)
{
    const float* obs    = (const float*)d_in[0];
    const float* enc_w1 = (const float*)d_in[1];
    const float* enc_b1 = (const float*)d_in[2];
    const float* enc_w2 = (const float*)d_in[3];
    const float* enc_b2 = (const float*)d_in[4];
    const float* inp_w  = (const float*)d_in[5];
    const float* inp_b  = (const float*)d_in[6];
    const float* out_w  = (const float*)d_in[7];
    const float* out_b  = (const float*)d_in[8];
    const float* int_w1 = (const float*)d_in[9];
    const float* int_b1 = (const float*)d_in[10];
    const float* ln_g   = (const float*)d_in[11];
    const float* ln_b   = (const float*)d_in[12];
    const float* int_w2 = (const float*)d_in[13];
    const float* int_b2 = (const float*)d_in[14];

    float* outE = (float*)d_out;
    const size_t esz = (size_t)MTOT * DOBS;
    float* outM = ((size_t)out_size > esz) ? outE + esz : nullptr;

    float *p_pack, *p_bc, *p_comb, *p_h, *p_qkv, *p_ctx, *p_z, *p_msgs;
    cudaGetSymbolAddress((void**)&p_pack, g_pack);
    cudaGetSymbolAddress((void**)&p_bc,   g_bc);
    cudaGetSymbolAddress((void**)&p_comb, g_Wcomb);
    cudaGetSymbolAddress((void**)&p_h,    g_h);
    cudaGetSymbolAddress((void**)&p_qkv,  g_qkv);
    cudaGetSymbolAddress((void**)&p_ctx,  g_ctx);
    cudaGetSymbolAddress((void**)&p_z,    g_z);
    cudaGetSymbolAddress((void**)&p_msgs, g_msgs_s);
    float* msgs = outM ? outM : p_msgs;

    // dynamic smem sizes (bytes)
    auto smB = [](int K, int N) { return (768 + 2 * 64 * 36 + 2 * 32 * N + 512) * 4; };
    const int sm_e1 = smB(128, 128);
    const int sm_e2 = smB(128, 64);
    const int sm_qk = smB(64, 192);
    const int sm_i1 = smB(192, 256);
    const int sm_i2 = smB(256, 128);
    const int sm_at = (64 * LD_QKV + 64 * LD_CTX) * 4;

    cudaFuncSetAttribute(gemm_pipe<128, 128, 0, 1>, cudaFuncAttributeMaxDynamicSharedMemorySize, sm_e1);
    cudaFuncSetAttribute(gemm_pipe<128, 64, 0, 0>,  cudaFuncAttributeMaxDynamicSharedMemorySize, sm_e2);
    cudaFuncSetAttribute(gemm_pipe<64, 192, 0, 0>,  cudaFuncAttributeMaxDynamicSharedMemorySize, sm_qk);
    cudaFuncSetAttribute(gemm_pipe<192, 256, 128, 2>, cudaFuncAttributeMaxDynamicSharedMemorySize, sm_i1);
    cudaFuncSetAttribute(gemm_pipe<256, 128, 0, 0>, cudaFuncAttributeMaxDynamicSharedMemorySize, sm_i2);
    cudaFuncSetAttribute(attn_kernel, cudaFuncAttributeMaxDynamicSharedMemorySize, sm_at);

    // weight prep
    prep_wc<<<64, 256>>>(out_w, out_b, int_w1, int_b1);
    combine_w<<<192, 256>>>(int_w1);
    pack_w<<<32, 256>>>(enc_w1, 128, 128, p_pack + P_E1);
    pack_w<<<16, 256>>>(enc_w2, 128, 64,  p_pack + P_E2);
    pack_w<<<24, 256>>>(inp_w,  64,  192, p_pack + P_QK);
    pack_w<<<96, 256>>>(p_comb, 192, 256, p_pack + P_I1);
    pack_w<<<64, 256>>>(int_w2, 256, 128, p_pack + P_I2);

    const int G = MTOT / 64;  // 4096 tiles

    // enc1: h = relu(obs @ W1 + b1)
    gemm_pipe<128, 128, 0, 1><<<G, 256, sm_e1>>>(obs, 128, nullptr, 0, p_pack + P_E1,
                                                 enc_b1, nullptr, nullptr, p_h);
    // enc2: msgs = h @ W2 + b2
    gemm_pipe<128, 64, 0, 0><<<G, 256, sm_e2>>>(p_h, 128, nullptr, 0, p_pack + P_E2,
                                                enc_b2, nullptr, nullptr, msgs);
    // qkv = msgs @ in_proj + b
    gemm_pipe<64, 192, 0, 0><<<G, 256, sm_qk>>>(msgs, 64, nullptr, 0, p_pack + P_QK,
                                                inp_b, nullptr, nullptr, p_qkv);
    // attention -> ctx
    attn_kernel<<<NBATCH, 256, sm_at>>>(p_qkv, p_ctx);
    // int1 (out-proj folded): z = LN(relu([obs|ctx] @ Wcomb + bc))
    gemm_pipe<192, 256, 128, 2><<<G, 256, sm_i1>>>(obs, 128, p_ctx, 64, p_pack + P_I1,
                                                   p_bc, ln_g, ln_b, p_z);
    // int2: enriched = z @ W2' + b2'
    gemm_pipe<256, 128, 0, 0><<<G, 256, sm_i2>>>(p_z, 256, nullptr, 0, p_pack + P_I2,
                                                 int_b2, nullptr, nullptr, outE);
}